// round 5
// baseline (speedup 1.0000x reference)
#include <cuda_runtime.h>
#include <cstdint>

#define B_   64
#define T_   512
#define H_   512
#define E_   128
#define C_   1000
#define G7   (7 * H_)    // 3584
#define OUTW (6 * H_)    // 3072
#define NCTA 128
#define NTHR 512

typedef unsigned long long ull;

// ---- device-global scratch ----
__device__ float g_tg[C_ * G7];        // table_gates = emb @ W1 + b   (14.3 MB)
__device__ float g_h[2][H_][B_];       // h_d double buffer, [buf][k][b]
__device__ int           g_count;
__device__ volatile int  g_sense;

// ---- helpers ----
__device__ __forceinline__ float sigf(float x)      { return 1.0f / (1.0f + expf(-x)); }
__device__ __forceinline__ float softplusf(float x) { return fmaxf(x, 0.0f) + log1pf(expf(-fabsf(x))); }

__device__ __forceinline__ void ffma2(ull& d, ull a, ull b)
{
    asm("fma.rn.f32x2 %0, %1, %2, %0;" : "+l"(d) : "l"(a), "l"(b));
}

__device__ __forceinline__ void grid_sync(int* sense)
{
    __threadfence();
    __syncthreads();
    if (threadIdx.x == 0) {
        int s = *sense ^ 1;
        *sense = s;
        if (atomicAdd(&g_count, 1) == (int)gridDim.x - 1) {
            g_count = 0;
            __threadfence();
            g_sense = s;
        } else {
            while (g_sense != s) { __nanosleep(64); }
            __threadfence();
        }
    }
    __syncthreads();
}

// =====================  Kernel 1: table_gates  =====================
__global__ void tg_kernel(const float* __restrict__ emb,
                          const float* __restrict__ W,
                          const float* __restrict__ bias)
{
    __shared__ float sh_e[16][E_];
    const int col = blockIdx.x * 256 + threadIdx.x;
    const int c0  = blockIdx.y * 16;

    for (int i = threadIdx.x; i < 16 * E_; i += 256) {
        int ci = i >> 7, e = i & 127;
        int c  = c0 + ci;
        sh_e[ci][e] = (c < C_) ? emb[c * E_ + e] : 0.0f;
    }
    __syncthreads();

    float acc[16];
#pragma unroll
    for (int i = 0; i < 16; ++i) acc[i] = 0.0f;

    for (int e = 0; e < E_; ++e) {
        float wv = W[e * G7 + col];
#pragma unroll
        for (int i = 0; i < 16; ++i) acc[i] = fmaf(sh_e[i][e], wv, acc[i]);
    }
    float bb = bias[col];
#pragma unroll
    for (int i = 0; i < 16; ++i) {
        int c = c0 + i;
        if (c < C_) g_tg[c * G7 + col] = acc[i] + bb;
    }
}

// =====================  Kernel 2: persistent recurrence  =====================
// 128 CTAs x 512 threads. CTA owns j in [4*cta, 4*cta+4) (28 gate cols).
// tid = ks*64 + r ; ks 0..7 (K-split 8), r = bg*4 + jl (bg 0..15 => 4 b's, jl 0..3).
// No h staging: h read straight from L2 via __ldcg (LDG.128, warp-dedup'd).
// smem: W dup-pair float2 [k][jl][g pad 8] (128KB resident) + reduction buffer.
#define WPAD_F  (512 * 4 * 8 * 2)     // 32768 floats = 131072 B
#define RSTR_U  15                    // ull per reduction slot (14 used + 1 pad)
#define RED_F   (NTHR * RSTR_U * 2)   // 15360 floats = 61440 B
#define SMEM_F  (WPAD_F + RED_F)
#define SMEM_BYTES (SMEM_F * 4)       // 192512 B

__global__ void __launch_bounds__(NTHR, 1)
rec_kernel(const int*   __restrict__ marks,
           const float* __restrict__ ts,
           const float* __restrict__ Wc,
           const float* __restrict__ init,
           float*       __restrict__ out)
{
    extern __shared__ float smem[];
    float* sh_W   = smem;
    float* sh_red = smem + WPAD_F;

    const int tid = threadIdx.x;
    const int cta = blockIdx.x;
    const int ks  = tid >> 6;      // 0..7
    const int r   = tid & 63;
    const int bg  = r >> 2;        // 0..15
    const int jl  = r & 3;

    // epilogue identity (threads 0..255): one (b, j) each
    const int eb  = tid >> 2;      // 0..63  (valid when tid < 256)
    const int ejl = tid & 3;
    const int ej  = cta * 4 + ejl;

    // ---- load resident W slice: [k][jl][g(8)] dup-pair float2, pad g=7 with 0 ----
    {
        float2* Wp = (float2*)sh_W;
        for (int idx = tid; idx < 512 * 32; idx += NTHR) {
            int k   = idx >> 5;
            int rem = idx & 31;
            int jj  = rem >> 3;
            int g   = rem & 7;
            float w = (g < 7) ? Wc[(size_t)(E_ + k) * G7 + g * H_ + cta * 4 + jj] : 0.0f;
            Wp[idx] = make_float2(w, w);
        }
    }

    // ---- init h buffer ----
    for (int idx = tid; idx < 4 * 64; idx += NTHR) {
        int jj = idx >> 6, bb = idx & 63;
        g_h[0][cta * 4 + jj][bb] = tanhf(init[cta * 4 + jj]);
    }

    // ---- output row t=0 ----
    for (int idx = tid; idx < 4 * 6 * 64; idx += NTHR) {
        int bb = idx & 63; int rest = idx >> 6;
        int f = rest % 6; int jj = rest / 6;
        int jg = cta * 4 + jj;
        float v;
        switch (f) {
            case 0:  v = tanhf(init[0 * H_ + jg]);     break;
            case 1:  v = sigf (init[5 * H_ + jg]);     break;
            case 2:  v = tanhf(init[2 * H_ + jg]);     break;
            case 3:  v = tanhf(init[3 * H_ + jg]);     break;
            case 4:  v = softplusf(init[4 * H_ + jg]); break;
            default: v = tanhf(init[1 * H_ + jg]);     break;
        }
        out[(size_t)bb * (513 * OUTW) + f * H_ + jg] = v;
    }

    // ---- per-(b,j) recurrent state (epilogue threads only use it) ----
    float c_d = tanhf(init[H_ + ej]);
    float c_b = tanhf(init[2 * H_ + ej]);

    int sense = 0;
    grid_sync(&sense);   // 1 + 511 = 512 flips per launch (even -> replay safe)

    const ull* wbase0 = (const ull*)sh_W + (size_t)(ks * 64 * 4 + jl) * 8;

    for (int t = 0; t < T_; ++t) {
        const float* hcur  = &g_h[t & 1][0][0];
        const float* hbase = hcur + (ks * 64) * 64 + bg * 4;

        // ---- epilogue prefetch (long-latency loads issued before matmul) ----
        float tsv = 0.f, tsp = 0.f, tg[7];
        if (tid < 256) {
            int m = __ldg(&marks[eb * T_ + t]);
            tsv   = __ldg(&ts[eb * T_ + t]);
            tsp   = (t > 0) ? __ldg(&ts[eb * T_ + t - 1]) : 0.0f;
            const float* tgp = g_tg + (size_t)m * G7 + ej;
#pragma unroll
            for (int g = 0; g < 7; ++g) tg[g] = __ldcg(tgp + g * H_);
        }

        ull acc[14];
#pragma unroll
        for (int i = 0; i < 14; ++i) acc[i] = 0ull;

#pragma unroll 4
        for (int kk = 0; kk < 64; ++kk) {
            float4 hf4 = __ldcg((const float4*)(hbase + kk * 64));
            ull hx = __double_as_longlong(*(const double*)&hf4.x);
            ull hy = __double_as_longlong(*(const double*)&hf4.z);
            const ull* wp = wbase0 + kk * 32;
            ulonglong2 w01 = *(const ulonglong2*)(wp);
            ulonglong2 w23 = *(const ulonglong2*)(wp + 2);
            ulonglong2 w45 = *(const ulonglong2*)(wp + 4);
            ull        w6  = wp[6];
            ffma2(acc[0],  w01.x, hx);  ffma2(acc[1],  w01.x, hy);
            ffma2(acc[2],  w01.y, hx);  ffma2(acc[3],  w01.y, hy);
            ffma2(acc[4],  w23.x, hx);  ffma2(acc[5],  w23.x, hy);
            ffma2(acc[6],  w23.y, hx);  ffma2(acc[7],  w23.y, hy);
            ffma2(acc[8],  w45.x, hx);  ffma2(acc[9],  w45.x, hy);
            ffma2(acc[10], w45.y, hx);  ffma2(acc[11], w45.y, hy);
            ffma2(acc[12], w6,    hx);  ffma2(acc[13], w6,    hy);
        }

        // ---- write partials, reduce 8-way across ks ----
        {
            ull* rb = (ull*)sh_red + (size_t)tid * RSTR_U;
#pragma unroll
            for (int i = 0; i < 14; ++i) rb[i] = acc[i];
        }
        __syncthreads();

        if (tid < 256) {
            const int bg2 = eb >> 2;
            const int p   = (eb >> 1) & 1;
            const int hf  = eb & 1;
            float a[7];
#pragma unroll
            for (int g = 0; g < 7; ++g) a[g] = 0.0f;
#pragma unroll
            for (int s = 0; s < 8; ++s) {
                const float* rp = sh_red + (size_t)(s * 64 + bg2 * 4 + ejl) * (RSTR_U * 2);
#pragma unroll
                for (int g = 0; g < 7; ++g) a[g] += rp[(g * 2 + p) * 2 + hf];
            }

            // ---- epilogue ----
            float dur = tsv - tsp;
            float gi  = sigf (a[0] + tg[0]);
            float gf  = sigf (a[1] + tg[1]);
            float gz  = tanhf(a[2] + tg[2]);
            float go  = sigf (a[3] + tg[3]);
            float gib = sigf (a[4] + tg[4]);
            float gfb = sigf (a[5] + tg[5]);
            float gd  = softplusf(a[6] + tg[6]);

            float c  = gf * c_d + gi * gz;
            float cb = gfb * c_b + gib * gz;
            float cd = cb + (c - cb) * expf(-gd * dur);
            float hd = go * tanhf(cd);
            c_d = cd; c_b = cb;

            size_t ob = (size_t)eb * (513 * OUTW) + (size_t)(t + 1) * OUTW + ej;
            out[ob]          = hd;
            out[ob + 1 * H_] = go;
            out[ob + 2 * H_] = cb;
            out[ob + 3 * H_] = c;
            out[ob + 4 * H_] = gd;
            out[ob + 5 * H_] = cd;

            g_h[(t + 1) & 1][ej][eb] = hd;
        }

        if (t != T_ - 1) grid_sync(&sense);
    }
}

// =====================  launch  =====================
extern "C" void kernel_launch(void* const* d_in, const int* in_sizes, int n_in,
                              void* d_out, int out_size)
{
    const int*   marks = (const int*)  d_in[0];
    const float* ts    = (const float*)d_in[1];
    const float* emb   = (const float*)d_in[2];
    const float* Wc    = (const float*)d_in[3];
    const float* bc    = (const float*)d_in[4];
    const float* init  = (const float*)d_in[5];
    float*       out   = (float*)d_out;

    dim3 g1(G7 / 256, (C_ + 15) / 16);
    tg_kernel<<<g1, 256>>>(emb, Wc, bc);

    cudaFuncSetAttribute(rec_kernel, cudaFuncAttributeMaxDynamicSharedMemorySize, SMEM_BYTES);
    rec_kernel<<<NCTA, NTHR, SMEM_BYTES>>>(marks, ts, Wc, init, out);
}

// round 6
// speedup vs baseline: 1.8015x; 1.8015x over previous
#include <cuda_runtime.h>
#include <cstdint>

#define B_   64
#define T_   512
#define H_   512
#define E_   128
#define C_   1000
#define G7   (7 * H_)    // 3584
#define OUTW (6 * H_)    // 3072
#define NCTA 128
#define NTHR 512

typedef unsigned long long ull;

// ---- device-global scratch ----
__device__ float g_tg[C_ * G7];        // table_gates = emb @ W1 + b   (14.3 MB)
__device__ float g_h[2][H_ * B_];      // h_d double buffer, [buf][k*64+b]
__device__ int           g_count;
__device__ volatile int  g_sense;

// ---- helpers ----
__device__ __forceinline__ float sigf(float x)      { return 1.0f / (1.0f + expf(-x)); }
__device__ __forceinline__ float softplusf(float x) { return fmaxf(x, 0.0f) + log1pf(expf(-fabsf(x))); }

__device__ __forceinline__ void ffma2(ull& d, ull a, ull b)
{
    asm("fma.rn.f32x2 %0, %1, %2, %0;" : "+l"(d) : "l"(a), "l"(b));
}
__device__ __forceinline__ ull dup2(float w)
{
    ull d; unsigned u = __float_as_uint(w);
    asm("mov.b64 %0, {%1, %1};" : "=l"(d) : "r"(u));
    return d;
}

__device__ __forceinline__ void grid_sync(int* sense)
{
    __threadfence();
    __syncthreads();
    if (threadIdx.x == 0) {
        int s = *sense ^ 1;
        *sense = s;
        if (atomicAdd(&g_count, 1) == (int)gridDim.x - 1) {
            g_count = 0;
            __threadfence();
            g_sense = s;
        } else {
            while (g_sense != s) { __nanosleep(64); }
            __threadfence();
        }
    }
    __syncthreads();
}

// =====================  Kernel 1: table_gates  =====================
__global__ void tg_kernel(const float* __restrict__ emb,
                          const float* __restrict__ W,
                          const float* __restrict__ bias)
{
    __shared__ float sh_e[16][E_];
    const int col = blockIdx.x * 256 + threadIdx.x;
    const int c0  = blockIdx.y * 16;

    for (int i = threadIdx.x; i < 16 * E_; i += 256) {
        int ci = i >> 7, e = i & 127;
        int c  = c0 + ci;
        sh_e[ci][e] = (c < C_) ? emb[c * E_ + e] : 0.0f;
    }
    __syncthreads();

    float acc[16];
#pragma unroll
    for (int i = 0; i < 16; ++i) acc[i] = 0.0f;

    for (int e = 0; e < E_; ++e) {
        float wv = W[e * G7 + col];
#pragma unroll
        for (int i = 0; i < 16; ++i) acc[i] = fmaf(sh_e[i][e], wv, acc[i]);
    }
    float bb = bias[col];
#pragma unroll
    for (int i = 0; i < 16; ++i) {
        int c = c0 + i;
        if (c < C_) g_tg[c * G7 + col] = acc[i] + bb;
    }
}

// =====================  Kernel 2: persistent recurrence  =====================
// 128 CTAs x 512 threads. CTA owns j in [4*cta, 4*cta+4) (28 gate cols), all 64 b.
// tid = ks*64 + r ; ks 0..7 ; r = bq*4 + jl (bq 0..15 -> b quad, jl 0..3).
// Warp = 8 bq x 4 jl: W LDS broadcast across bq, h LDS broadcast across jl.
// W scalar smem [k][jl][g pad8] (64KB). h staged to smem in 2 pipelined chunks
// (128KB, aliased by the reduction buffer after compute).
#define WS_F    (512 * 32)            // 16384 floats = 65536 B
#define HS_F    (512 * 64)            // 32768 floats = 131072 B
#define SMEM_BYTES ((WS_F + HS_F) * 4)   // 196608 B
#define RSTRIDE 30                    // floats per reduction record (14 ull + pad)

__global__ void __launch_bounds__(NTHR, 1)
rec_kernel(const int*   __restrict__ marks,
           const float* __restrict__ ts,
           const float* __restrict__ Wc,
           const float* __restrict__ init,
           float*       __restrict__ out)
{
    extern __shared__ float smem[];
    float* sh_W   = smem;            // [k][jl*8 + g]
    float* sh_h   = smem + WS_F;     // [k][b]
    float* sh_red = sh_h;            // alias: used only after h consumed

    const int tid = threadIdx.x;
    const int cta = blockIdx.x;
    const int ks  = tid >> 6;        // 0..7
    const int r   = tid & 63;
    const int jl  = r & 3;
    const int q4  = (r >> 2) * 4;    // b-quad base (0,4,...,60)

    // epilogue identity (threads 0..255): one (b, j) each
    const int eb  = tid >> 2;        // 0..63
    const int ejl = tid & 3;
    const int ej  = cta * 4 + ejl;

    // ---- load resident W slice: [k][jl][g pad8] scalar ----
    for (int idx = tid; idx < WS_F; idx += NTHR) {
        int k = idx >> 5; int rem = idx & 31;
        int jj = rem >> 3, g = rem & 7;
        sh_W[idx] = (g < 7) ? Wc[(size_t)(E_ + k) * G7 + g * H_ + cta * 4 + jj] : 0.0f;
    }

    // ---- init h buffer ----
    for (int idx = tid; idx < 4 * 64; idx += NTHR) {
        int jj = idx >> 6, bb = idx & 63;
        g_h[0][(cta * 4 + jj) * B_ + bb] = tanhf(init[cta * 4 + jj]);
    }

    // ---- output row t=0 ----
    for (int idx = tid; idx < 4 * 6 * 64; idx += NTHR) {
        int bb = idx & 63; int rest = idx >> 6;
        int f = rest % 6; int jj = rest / 6;
        int jg = cta * 4 + jj;
        float v;
        switch (f) {
            case 0:  v = tanhf(init[0 * H_ + jg]);     break;
            case 1:  v = sigf (init[5 * H_ + jg]);     break;
            case 2:  v = tanhf(init[2 * H_ + jg]);     break;
            case 3:  v = tanhf(init[3 * H_ + jg]);     break;
            case 4:  v = softplusf(init[4 * H_ + jg]); break;
            default: v = tanhf(init[1 * H_ + jg]);     break;
        }
        out[(size_t)bb * (513 * OUTW) + f * H_ + jg] = v;
    }

    // ---- per-(b,j) recurrent state (epilogue threads) ----
    float c_d = tanhf(init[H_ + ej]);
    float c_b = tanhf(init[2 * H_ + ej]);

    int sense = 0;
    grid_sync(&sense);   // 1 + 511 = 512 flips (even -> graph replay safe)

    const float* hb = sh_h + q4;
    const float* wb = sh_W + jl * 8;

#define STEP_K(k) do {                                                          \
        ull hx = *(const ull*)(hb + (k) * 64);                                  \
        ull hy = *(const ull*)(hb + (k) * 64 + 2);                              \
        const float* wp = wb + (k) * 32;                                        \
        float4 wA = *(const float4*)wp;                                         \
        float2 wB = *(const float2*)(wp + 4);                                   \
        float  wC = wp[6];                                                      \
        ull w;                                                                  \
        w = dup2(wA.x); ffma2(acc[0],  w, hx); ffma2(acc[1],  w, hy);           \
        w = dup2(wA.y); ffma2(acc[2],  w, hx); ffma2(acc[3],  w, hy);           \
        w = dup2(wA.z); ffma2(acc[4],  w, hx); ffma2(acc[5],  w, hy);           \
        w = dup2(wA.w); ffma2(acc[6],  w, hx); ffma2(acc[7],  w, hy);           \
        w = dup2(wB.x); ffma2(acc[8],  w, hx); ffma2(acc[9],  w, hy);           \
        w = dup2(wB.y); ffma2(acc[10], w, hx); ffma2(acc[11], w, hy);           \
        w = dup2(wC);   ffma2(acc[12], w, hx); ffma2(acc[13], w, hy);           \
    } while (0)

    for (int t = 0; t < T_; ++t) {
        const float4* hbuf4 = (const float4*)&g_h[t & 1][0];
        float4*       shh4  = (float4*)sh_h;

        // ---- epilogue prefetch (independent L2 loads, consumed much later) ----
        float tsv = 0.f, tsp = 0.f, tg[7];
        if (tid < 256) {
            int m = __ldg(&marks[eb * T_ + t]);
            tsv   = __ldg(&ts[eb * T_ + t]);
            tsp   = (t > 0) ? __ldg(&ts[eb * T_ + t - 1]) : 0.0f;
            const float* tgp = g_tg + (size_t)m * G7 + ej;
#pragma unroll
            for (int g = 0; g < 7; ++g) tg[g] = __ldcg(tgp + g * H_);
        }

        ull acc[14];
#pragma unroll
        for (int i = 0; i < 14; ++i) acc[i] = 0ull;

        // ---- stage chunk 0 (k 0..255) ----
        {
            float4 s0[8];
#pragma unroll
            for (int i = 0; i < 8; ++i) s0[i] = __ldcg(hbuf4 + i * NTHR + tid);
#pragma unroll
            for (int i = 0; i < 8; ++i) shh4[i * NTHR + tid] = s0[i];
        }
        __syncthreads();

        // ---- prefetch chunk 1 (k 256..511) into regs ----
        float4 s1[8];
#pragma unroll
        for (int i = 0; i < 8; ++i) s1[i] = __ldcg(hbuf4 + 4096 + i * NTHR + tid);

        // ---- compute chunk 0 : this thread's k = ks*32 + m ----
        {
            const int k0 = ks * 32;
#pragma unroll 8
            for (int m = 0; m < 32; ++m) STEP_K(k0 + m);
        }

        // ---- store chunk 1, compute chunk 1 ----
#pragma unroll
        for (int i = 0; i < 8; ++i) shh4[4096 + i * NTHR + tid] = s1[i];
        __syncthreads();
        {
            const int k0 = 256 + ks * 32;
#pragma unroll 8
            for (int m = 0; m < 32; ++m) STEP_K(k0 + m);
        }

        // ---- write partials (red aliases chunk-0 area; chunk-1 reads are disjoint) ----
        {
            ull* rb = (ull*)(sh_red + (size_t)tid * RSTRIDE);
#pragma unroll
            for (int i = 0; i < 14; ++i) rb[i] = acc[i];
        }
        __syncthreads();

        if (tid < 256) {
            const int p  = (eb >> 1) & 1;
            const int hf = eb & 1;
            float a[7];
#pragma unroll
            for (int g = 0; g < 7; ++g) a[g] = 0.0f;
#pragma unroll
            for (int s = 0; s < 8; ++s) {
                const float* rp = sh_red + (size_t)(s * 64 + (eb >> 2) * 4 + ejl) * RSTRIDE;
#pragma unroll
                for (int g = 0; g < 7; ++g) a[g] += rp[(g * 2 + p) * 2 + hf];
            }

            // ---- epilogue ----
            float dur = tsv - tsp;
            float gi  = sigf (a[0] + tg[0]);
            float gf  = sigf (a[1] + tg[1]);
            float gz  = tanhf(a[2] + tg[2]);
            float go  = sigf (a[3] + tg[3]);
            float gib = sigf (a[4] + tg[4]);
            float gfb = sigf (a[5] + tg[5]);
            float gd  = softplusf(a[6] + tg[6]);

            float c  = gf * c_d + gi * gz;
            float cb = gfb * c_b + gib * gz;
            float cd = cb + (c - cb) * expf(-gd * dur);
            float hd = go * tanhf(cd);
            c_d = cd; c_b = cb;

            size_t ob = (size_t)eb * (513 * OUTW) + (size_t)(t + 1) * OUTW + ej;
            out[ob]          = hd;
            out[ob + 1 * H_] = go;
            out[ob + 2 * H_] = cb;
            out[ob + 3 * H_] = c;
            out[ob + 4 * H_] = gd;
            out[ob + 5 * H_] = cd;

            g_h[(t + 1) & 1][ej * B_ + eb] = hd;
        }

        if (t != T_ - 1) grid_sync(&sense);
    }
#undef STEP_K
}

// =====================  launch  =====================
extern "C" void kernel_launch(void* const* d_in, const int* in_sizes, int n_in,
                              void* d_out, int out_size)
{
    const int*   marks = (const int*)  d_in[0];
    const float* ts    = (const float*)d_in[1];
    const float* emb   = (const float*)d_in[2];
    const float* Wc    = (const float*)d_in[3];
    const float* bc    = (const float*)d_in[4];
    const float* init  = (const float*)d_in[5];
    float*       out   = (float*)d_out;

    dim3 g1(G7 / 256, (C_ + 15) / 16);
    tg_kernel<<<g1, 256>>>(emb, Wc, bc);

    cudaFuncSetAttribute(rec_kernel, cudaFuncAttributeMaxDynamicSharedMemorySize, SMEM_BYTES);
    rec_kernel<<<NCTA, NTHR, SMEM_BYTES>>>(marks, ts, Wc, init, out);
}